// round 1
// baseline (speedup 1.0000x reference)
#include <cuda_runtime.h>
#include <math.h>

#define L    8192
#define DIN  128
#define HH   64
#define WW   128
#define NCH  64
#define LC   128

// ---------------- scratch (device globals; no allocation) ----------------
__device__ float g_hxp[DIN * L];        // after w_proj GEMM       [o][l]
__device__ float g_xp [DIN * L];        // xp pre-conv             [d][l]
__device__ float g_zt [L * DIN];        // z transposed            [l][d]
__device__ float g_xpa[DIN * L];        // xp after conv+silu      [d][l]
__device__ float g_xsr[L * DIN];        // row-major scan input    [l][d]
__device__ float g_xsc[L * DIN];        // col-major scan input    [lc][d]
__device__ float g_dbc[4 * 40 * L];     // x_proj output           [k][r][l]
__device__ float g_dtv[4 * L * DIN];    // softplus dt             [k][l][d]
__device__ float g_bc [4 * L * 32];     // B(16),C(16) per pos     [k][l][32]
__device__ float g_S  [4 * DIN * NCH];          // sum dt per chunk
__device__ float g_F  [4 * DIN * NCH * 16];     // chunk-local final state
__device__ float g_hi [4 * DIN * NCH * 16];     // chunk initial state
__device__ float g_ys [4 * L * DIN];    // scan outputs            [k][l][d]
__device__ float g_yg [L * DIN];        // merged+LN+gated         [l][d]
__device__ int   g_intA;

// ---------------- A-structure check: A_log == log(1..16)? ----------------
__global__ void k_checkA(const float* __restrict__ A_log) {
    __shared__ int bad;
    if (threadIdx.x == 0) bad = 0;
    __syncthreads();
    for (int i = threadIdx.x; i < 4 * DIN * 16; i += blockDim.x) {
        int n = i & 15;
        float ref = logf((float)(n + 1));
        if (fabsf(A_log[i] - ref) > 1e-5f) bad = 1;
    }
    __syncthreads();
    if (threadIdx.x == 0) g_intA = bad ? 0 : 1;
}

// ---------------- GEMM1: hxp = w_proj @ concat(h,x) + b_proj -------------
__global__ __launch_bounds__(256) void k_gemm1(
    const float* __restrict__ hsrc, const float* __restrict__ xsrc,
    const float* __restrict__ w,    const float* __restrict__ bias) {
    __shared__ float As[16][64];
    __shared__ float Bs[16][64];
    int tid = threadIdx.x;
    int tx = tid & 15, ty = tid >> 4;
    int l0 = blockIdx.x * 64, o0 = blockIdx.y * 64;
    int arow = tid >> 2, ak = (tid & 3) * 4;
    int bk = tid >> 4, bj = (tid & 15) * 4;
    float acc[4][4] = {};
    for (int k0 = 0; k0 < 320; k0 += 16) {
        float4 av = *(const float4*)(w + (o0 + arow) * 320 + k0 + ak);
        As[ak + 0][arow] = av.x; As[ak + 1][arow] = av.y;
        As[ak + 2][arow] = av.z; As[ak + 3][arow] = av.w;
        int c = k0 + bk;
        const float* bp = (c < 128) ? (hsrc + c * L) : (xsrc + (c - 128) * L);
        *(float4*)&Bs[bk][bj] = *(const float4*)(bp + l0 + bj);
        __syncthreads();
#pragma unroll
        for (int kk = 0; kk < 16; kk++) {
            float4 a = *(float4*)&As[kk][ty * 4];
            float4 b = *(float4*)&Bs[kk][tx * 4];
            float ar[4] = {a.x, a.y, a.z, a.w};
            float br[4] = {b.x, b.y, b.z, b.w};
#pragma unroll
            for (int r = 0; r < 4; r++)
#pragma unroll
                for (int cc = 0; cc < 4; cc++)
                    acc[r][cc] = fmaf(ar[r], br[cc], acc[r][cc]);
        }
        __syncthreads();
    }
#pragma unroll
    for (int r = 0; r < 4; r++) {
        int o = o0 + ty * 4 + r;
        float bv = bias[o];
#pragma unroll
        for (int cc = 0; cc < 4; cc++)
            g_hxp[o * L + l0 + tx * 4 + cc] = acc[r][cc] + bv;
    }
}

// ---------------- GEMM2: xz = w_in @ hxp; split into xp / z^T ------------
__global__ __launch_bounds__(256) void k_gemm2(const float* __restrict__ w) {
    __shared__ float As[16][64];
    __shared__ float Bs[16][64];
    int tid = threadIdx.x;
    int tx = tid & 15, ty = tid >> 4;
    int l0 = blockIdx.x * 64, o0 = blockIdx.y * 64;
    int arow = tid >> 2, ak = (tid & 3) * 4;
    int bk = tid >> 4, bj = (tid & 15) * 4;
    float acc[4][4] = {};
    for (int k0 = 0; k0 < 128; k0 += 16) {
        float4 av = *(const float4*)(w + (o0 + arow) * 128 + k0 + ak);
        As[ak + 0][arow] = av.x; As[ak + 1][arow] = av.y;
        As[ak + 2][arow] = av.z; As[ak + 3][arow] = av.w;
        *(float4*)&Bs[bk][bj] = *(const float4*)(g_hxp + (k0 + bk) * L + l0 + bj);
        __syncthreads();
#pragma unroll
        for (int kk = 0; kk < 16; kk++) {
            float4 a = *(float4*)&As[kk][ty * 4];
            float4 b = *(float4*)&Bs[kk][tx * 4];
            float ar[4] = {a.x, a.y, a.z, a.w};
            float br[4] = {b.x, b.y, b.z, b.w};
#pragma unroll
            for (int r = 0; r < 4; r++)
#pragma unroll
                for (int cc = 0; cc < 4; cc++)
                    acc[r][cc] = fmaf(ar[r], br[cc], acc[r][cc]);
        }
        __syncthreads();
    }
#pragma unroll
    for (int r = 0; r < 4; r++) {
        int o = o0 + ty * 4 + r;
#pragma unroll
        for (int cc = 0; cc < 4; cc++) {
            int l = l0 + tx * 4 + cc;
            float v = acc[r][cc];
            if (o < 128) g_xp[o * L + l] = v;
            else         g_zt[l * DIN + (o - 128)] = v;
        }
    }
}

// ---------------- depthwise 3x3 conv + bias + SiLU -----------------------
__global__ __launch_bounds__(256) void k_conv(
    const float* __restrict__ wc, const float* __restrict__ bc) {
    int idx = blockIdx.x * 256 + threadIdx.x;
    if (idx >= DIN * L) return;
    int d = idx >> 13, l = idx & (L - 1);
    int hh = l >> 7, ww = l & 127;
    const float* src = g_xp + (d << 13);
    const float* w9 = wc + d * 9;
    float acc = bc[d];
#pragma unroll
    for (int kh = 0; kh < 3; kh++) {
        int y = hh + kh - 1;
        if (y < 0 || y >= HH) continue;
#pragma unroll
        for (int kw = 0; kw < 3; kw++) {
            int xw = ww + kw - 1;
            if (xw < 0 || xw >= WW) continue;
            acc = fmaf(src[y * WW + xw], w9[kh * 3 + kw], acc);
        }
    }
    float s = acc / (1.f + __expf(-acc));
    g_xpa[idx] = s;
}

// ---------------- transpose: xpa[d][l] -> xsr[l][d], xsc[lc][d] ----------
__global__ void k_transpose() {
    __shared__ float t[32][33];
    int l0 = blockIdx.x * 32, d0 = blockIdx.y * 32;
    int tx = threadIdx.x, ty = threadIdx.y;  // 32 x 8
#pragma unroll
    for (int j = 0; j < 4; j++)
        t[ty + 8 * j][tx] = g_xpa[(d0 + ty + 8 * j) * L + l0 + tx];
    __syncthreads();
#pragma unroll
    for (int j = 0; j < 4; j++) {
        int l = l0 + ty + 8 * j;
        float v = t[tx][ty + 8 * j];
        g_xsr[l * DIN + d0 + tx] = v;
        int hh = l >> 7, ww = l & 127;
        g_xsc[(ww * HH + hh) * DIN + d0 + tx] = v;
    }
}

// ---------------- x_proj: dbc[k] = x_proj_w[k] @ xs[k]  (NT GEMM) --------
__global__ __launch_bounds__(256) void k_dbc(const float* __restrict__ xpw) {
    int k = blockIdx.z;
    const float* A = xpw + k * 40 * 128;
    const float* Bsrc = (k & 1) ? g_xsc : g_xsr;
    bool rev = (k >= 2);
    __shared__ float As[16][64];
    __shared__ float Bs[16][64];
    int tid = threadIdx.x;
    int tx = tid & 15, ty = tid >> 4;
    int l0 = blockIdx.x * 64;
    int arow = tid >> 2, ak = (tid & 3) * 4;
    float acc[4][4] = {};
    for (int k0 = 0; k0 < 128; k0 += 16) {
        int rr = arow < 40 ? arow : 39;
        float4 av = *(const float4*)(A + rr * 128 + k0 + ak);
        As[ak + 0][arow] = av.x; As[ak + 1][arow] = av.y;
        As[ak + 2][arow] = av.z; As[ak + 3][arow] = av.w;
        int ln = l0 + arow;
        int lsrc = rev ? (L - 1 - ln) : ln;
        float4 bv = *(const float4*)(Bsrc + lsrc * 128 + k0 + ak);
        Bs[ak + 0][arow] = bv.x; Bs[ak + 1][arow] = bv.y;
        Bs[ak + 2][arow] = bv.z; Bs[ak + 3][arow] = bv.w;
        __syncthreads();
#pragma unroll
        for (int kk = 0; kk < 16; kk++) {
            float4 a = *(float4*)&As[kk][ty * 4];
            float4 b = *(float4*)&Bs[kk][tx * 4];
            float ar[4] = {a.x, a.y, a.z, a.w};
            float br[4] = {b.x, b.y, b.z, b.w};
#pragma unroll
            for (int r = 0; r < 4; r++)
#pragma unroll
                for (int cc = 0; cc < 4; cc++)
                    acc[r][cc] = fmaf(ar[r], br[cc], acc[r][cc]);
        }
        __syncthreads();
    }
#pragma unroll
    for (int r = 0; r < 4; r++) {
        int m = ty * 4 + r;
        if (m < 40) {
#pragma unroll
            for (int cc = 0; cc < 4; cc++)
                g_dbc[(k * 40 + m) * L + l0 + tx * 4 + cc] = acc[r][cc];
        }
    }
}

// ---------------- dt = softplus(dt_w @ dts + dt_b); pack B,C -------------
__global__ __launch_bounds__(128) void k_dt(
    const float* __restrict__ dtw, const float* __restrict__ dtbias) {
    int k = blockIdx.y;
    int l0 = blockIdx.x * 32;
    int d = threadIdx.x;
    __shared__ float sd[40][33];
    for (int i = threadIdx.x; i < 40 * 32; i += 128) {
        int r = i >> 5, j = i & 31;
        sd[r][j] = g_dbc[(k * 40 + r) * L + l0 + j];
    }
    __syncthreads();
    float wreg[8];
#pragma unroll
    for (int r = 0; r < 8; r++) wreg[r] = dtw[(k * DIN + d) * 8 + r];
    float bv = dtbias[k * DIN + d];
    for (int j = 0; j < 32; j++) {
        float acc = bv;
#pragma unroll
        for (int r = 0; r < 8; r++) acc = fmaf(wreg[r], sd[r][j], acc);
        float sp = (acc > 20.f) ? acc : log1pf(__expf(acc));
        g_dtv[(k * L + l0 + j) * DIN + d] = sp;
    }
    for (int i = threadIdx.x; i < 32 * 32; i += 128) {
        int n = i >> 5, j = i & 31;
        g_bc[(k * L + l0 + j) * 32 + n] = sd[8 + n][j];
    }
}

// ---------------- a_n = exp(dt * A_n) helpers ----------------------------
__device__ __forceinline__ void compute_a(float dtv, const float* An, bool ia,
                                          float* a) {
    if (ia) {  // A_n = -(n+1): a_n = r^(n+1), r = exp(-dt)
        float r1 = __expf(-dtv);
        float r2 = r1 * r1, r4 = r2 * r2, r8 = r4 * r4;
        a[0] = r1;       a[1] = r2;       a[2] = r2 * r1;  a[3] = r4;
        a[4] = r4 * r1;  a[5] = r4 * r2;  a[6] = r4 * a[2]; a[7] = r8;
        a[8] = r8 * r1;  a[9] = r8 * r2;  a[10] = r8 * a[2]; a[11] = r8 * r4;
        a[12] = r8 * a[4]; a[13] = r8 * a[5]; a[14] = r8 * a[6]; a[15] = r8 * r8;
    } else {
#pragma unroll
        for (int n = 0; n < 16; n++) a[n] = __expf(An[n] * dtv);
    }
}

// ---------------- scan phase 1: chunk-local (F, sum-dt) ------------------
__global__ __launch_bounds__(128) void k_scan1(const float* __restrict__ A_log) {
    int c = blockIdx.x, k = blockIdx.y, d = threadIdx.x;
    bool ia = (g_intA != 0);
    float An[16];
    if (!ia) {
#pragma unroll
        for (int n = 0; n < 16; n++) An[n] = -__expf(A_log[(k * DIN + d) * 16 + n]);
    }
    const float* usrc = (k & 1) ? g_xsc : g_xsr;
    bool rev = (k >= 2);
    float hr[16];
#pragma unroll
    for (int n = 0; n < 16; n++) hr[n] = 0.f;
    float S = 0.f;
    const float* dtp = g_dtv + k * L * DIN;
    for (int i = 0; i < LC; i++) {
        int l = c * LC + i;
        float dtv = dtp[l * DIN + d];
        int lu = rev ? (L - 1 - l) : l;
        float uv = usrc[lu * DIN + d];
        float du = dtv * uv;
        S += dtv;
        const float4* bp = (const float4*)(g_bc + (k * L + l) * 32);
        float4 b0 = bp[0], b1 = bp[1], b2 = bp[2], b3 = bp[3];
        float bb[16] = {b0.x, b0.y, b0.z, b0.w, b1.x, b1.y, b1.z, b1.w,
                        b2.x, b2.y, b2.z, b2.w, b3.x, b3.y, b3.z, b3.w};
        float a[16];
        compute_a(dtv, An, ia, a);
#pragma unroll
        for (int n = 0; n < 16; n++) hr[n] = fmaf(a[n], hr[n], du * bb[n]);
    }
    int base = (k * DIN + d) * NCH + c;
    g_S[base] = S;
#pragma unroll
    for (int n = 0; n < 16; n++) g_F[base * 16 + n] = hr[n];
}

// ---------------- scan phase 2: cross-chunk prefix -----------------------
__global__ __launch_bounds__(256) void k_scan2(const float* __restrict__ A_log) {
    int n = threadIdx.x & 15;
    int d = blockIdx.x * 16 + (threadIdx.x >> 4);
    int k = blockIdx.y;
    bool ia = (g_intA != 0);
    float An = ia ? -(float)(n + 1) : -__expf(A_log[(k * DIN + d) * 16 + n]);
    float h = 0.f;
    int base = (k * DIN + d) * NCH;
    for (int c = 0; c < NCH; c++) {
        g_hi[(base + c) * 16 + n] = h;
        float P = __expf(An * g_S[base + c]);
        h = fmaf(P, h, g_F[(base + c) * 16 + n]);
    }
}

// ---------------- scan phase 3: replay with init, emit y -----------------
__global__ __launch_bounds__(128) void k_scan3(
    const float* __restrict__ A_log, const float* __restrict__ Dssm) {
    int c = blockIdx.x, k = blockIdx.y, d = threadIdx.x;
    bool ia = (g_intA != 0);
    float An[16];
    if (!ia) {
#pragma unroll
        for (int n = 0; n < 16; n++) An[n] = -__expf(A_log[(k * DIN + d) * 16 + n]);
    }
    const float* usrc = (k & 1) ? g_xsc : g_xsr;
    bool rev = (k >= 2);
    float Dv = Dssm[k * DIN + d];
    int base = (k * DIN + d) * NCH + c;
    float hr[16];
#pragma unroll
    for (int n = 0; n < 16; n++) hr[n] = g_hi[base * 16 + n];
    const float* dtp = g_dtv + k * L * DIN;
    for (int i = 0; i < LC; i++) {
        int l = c * LC + i;
        float dtv = dtp[l * DIN + d];
        int lu = rev ? (L - 1 - l) : l;
        float uv = usrc[lu * DIN + d];
        float du = dtv * uv;
        const float4* bp = (const float4*)(g_bc + (k * L + l) * 32);
        float4 b0 = bp[0], b1 = bp[1], b2 = bp[2], b3 = bp[3];
        float4 c0 = bp[4], c1 = bp[5], c2 = bp[6], c3 = bp[7];
        float bb[16] = {b0.x, b0.y, b0.z, b0.w, b1.x, b1.y, b1.z, b1.w,
                        b2.x, b2.y, b2.z, b2.w, b3.x, b3.y, b3.z, b3.w};
        float cc[16] = {c0.x, c0.y, c0.z, c0.w, c1.x, c1.y, c1.z, c1.w,
                        c2.x, c2.y, c2.z, c2.w, c3.x, c3.y, c3.z, c3.w};
        float a[16];
        compute_a(dtv, An, ia, a);
        float y4[4] = {0.f, 0.f, 0.f, 0.f};
#pragma unroll
        for (int n = 0; n < 16; n++) {
            hr[n] = fmaf(a[n], hr[n], du * bb[n]);
            y4[n & 3] = fmaf(hr[n], cc[n], y4[n & 3]);
        }
        float y = fmaf(Dv, uv, (y4[0] + y4[1]) + (y4[2] + y4[3]));
        g_ys[(k * L + l) * DIN + d] = y;
    }
}

// ---------------- cross-merge + LayerNorm + SiLU(z) gate -----------------
__global__ __launch_bounds__(128) void k_merge(
    const float* __restrict__ lng, const float* __restrict__ lnb) {
    int l = blockIdx.x, d = threadIdx.x;
    int hh = l >> 7, ww = l & 127;
    int lc = ww * HH + hh;
    float y = g_ys[(0 * L + l) * DIN + d]
            + g_ys[(2 * L + (L - 1 - l)) * DIN + d]
            + g_ys[(1 * L + lc) * DIN + d]
            + g_ys[(3 * L + (L - 1 - lc)) * DIN + d];
    float s = y, s2 = y * y;
#pragma unroll
    for (int o = 16; o > 0; o >>= 1) {
        s  += __shfl_xor_sync(0xffffffffu, s, o);
        s2 += __shfl_xor_sync(0xffffffffu, s2, o);
    }
    __shared__ float rs[4], rs2[4];
    int wid = d >> 5;
    if ((d & 31) == 0) { rs[wid] = s; rs2[wid] = s2; }
    __syncthreads();
    float sum  = rs[0] + rs[1] + rs[2] + rs[3];
    float sum2 = rs2[0] + rs2[1] + rs2[2] + rs2[3];
    float mu = sum * (1.f / 128.f);
    float var = sum2 * (1.f / 128.f) - mu * mu;
    float gv = (y - mu) * rsqrtf(var + 1e-5f) * lng[d] + lnb[d];
    float z = g_zt[l * DIN + d];
    float sz = z / (1.f + __expf(-z));
    g_yg[l * DIN + d] = gv * sz;
}

// ---------------- final: out = h + tanh(w_out @ yg)  (NT GEMM) -----------
__global__ __launch_bounds__(256) void k_final(
    const float* __restrict__ wout, const float* __restrict__ hsrc,
    float* __restrict__ out) {
    __shared__ float As[16][64];
    __shared__ float Bs[16][64];
    int tid = threadIdx.x;
    int tx = tid & 15, ty = tid >> 4;
    int l0 = blockIdx.x * 64, o0 = blockIdx.y * 64;
    int arow = tid >> 2, ak = (tid & 3) * 4;
    float acc[4][4] = {};
    for (int k0 = 0; k0 < 128; k0 += 16) {
        float4 av = *(const float4*)(wout + (o0 + arow) * 128 + k0 + ak);
        As[ak + 0][arow] = av.x; As[ak + 1][arow] = av.y;
        As[ak + 2][arow] = av.z; As[ak + 3][arow] = av.w;
        float4 bv = *(const float4*)(g_yg + (l0 + arow) * 128 + k0 + ak);
        Bs[ak + 0][arow] = bv.x; Bs[ak + 1][arow] = bv.y;
        Bs[ak + 2][arow] = bv.z; Bs[ak + 3][arow] = bv.w;
        __syncthreads();
#pragma unroll
        for (int kk = 0; kk < 16; kk++) {
            float4 a = *(float4*)&As[kk][ty * 4];
            float4 b = *(float4*)&Bs[kk][tx * 4];
            float ar[4] = {a.x, a.y, a.z, a.w};
            float br[4] = {b.x, b.y, b.z, b.w};
#pragma unroll
            for (int r = 0; r < 4; r++)
#pragma unroll
                for (int cc = 0; cc < 4; cc++)
                    acc[r][cc] = fmaf(ar[r], br[cc], acc[r][cc]);
        }
        __syncthreads();
    }
#pragma unroll
    for (int r = 0; r < 4; r++) {
        int o = o0 + ty * 4 + r;
#pragma unroll
        for (int cc = 0; cc < 4; cc++) {
            int l = l0 + tx * 4 + cc;
            out[o * L + l] = hsrc[o * L + l] + tanhf(acc[r][cc]);
        }
    }
}

// ---------------- launch ----------------
extern "C" void kernel_launch(void* const* d_in, const int* in_sizes, int n_in,
                              void* d_out, int out_size) {
    const float* h       = (const float*)d_in[0];
    const float* x       = (const float*)d_in[1];
    const float* w_proj  = (const float*)d_in[2];
    const float* b_proj  = (const float*)d_in[3];
    const float* w_in    = (const float*)d_in[4];
    const float* w_conv  = (const float*)d_in[5];
    const float* b_conv  = (const float*)d_in[6];
    const float* x_proj_w= (const float*)d_in[7];
    const float* dt_w    = (const float*)d_in[8];
    const float* dt_b    = (const float*)d_in[9];
    const float* A_log   = (const float*)d_in[10];
    const float* D_ssm   = (const float*)d_in[11];
    const float* ln_g    = (const float*)d_in[12];
    const float* ln_b    = (const float*)d_in[13];
    const float* w_out   = (const float*)d_in[14];
    float* out = (float*)d_out;

    k_checkA   <<<1, 256>>>(A_log);
    k_gemm1    <<<dim3(128, 2), 256>>>(h, x, w_proj, b_proj);
    k_gemm2    <<<dim3(128, 4), 256>>>(w_in);
    k_conv     <<<(DIN * L + 255) / 256, 256>>>(w_conv, b_conv);
    k_transpose<<<dim3(256, 4), dim3(32, 8)>>>();
    k_dbc      <<<dim3(128, 1, 4), 256>>>(x_proj_w);
    k_dt       <<<dim3(256, 4), 128>>>(dt_w, dt_b);
    k_scan1    <<<dim3(NCH, 4), 128>>>(A_log);
    k_scan2    <<<dim3(8, 4), 256>>>(A_log);
    k_scan3    <<<dim3(NCH, 4), 128>>>(A_log, D_ssm);
    k_merge    <<<L, 128>>>(ln_g, ln_b);
    k_final    <<<dim3(128, 2), 256>>>(w_out, h, out);
}